// round 1
// baseline (speedup 1.0000x reference)
#include <cuda_runtime.h>
#include <math.h>

// Problem constants (fixed by the dataset)
#define DM   1536          // model dim
#define NHD  16            // heads
#define HD   96            // head dim
#define LT   2048          // joint sequence length (N + M)
#define NB   2             // batch
#define RT   2048          // rows per stage-A GEMM (B*N = B*M)
#define EPSF 1e-6f
#define SCALEF 0.10206207261596575f   // 96^-0.5

// ----------------------------------------------------------------------------
// Scratch (static __device__ globals -- no runtime allocation allowed)
// ----------------------------------------------------------------------------
__device__ float g_tmp[6][RT * DM];              // cond_q, cond_k, cond_v, x_q, x_k, x_v (pre-norm)
__device__ float g_q[NB * NHD * LT * HD];        // [B, NH, L, HD]
__device__ float g_kk[NB * NHD * LT * HD];
__device__ float g_v[NB * NHD * LT * HD];
__device__ float g_attn[NB * LT * DM];           // [B, L, NH*HD] token-major

// ----------------------------------------------------------------------------
// SGEMM: C[2048 x 1536] = A[2048 x 1536] * B[1536 x 1536]   (all row-major)
// Row r of A maps to A + (r / rowsPerBatch)*batchStrideA + (r % rowsPerBatch)*K
// 128x128 tile, BK=8, 256 threads, 8x8 per-thread micro-tile.
// ----------------------------------------------------------------------------
__global__ __launch_bounds__(256) void sgemm_kernel(
    const float* __restrict__ A, const float* __restrict__ B, float* __restrict__ C,
    int rowsPerBatch, size_t batchStrideA)
{
    const int K = DM, N = DM;
    __shared__ float As[8][128];
    __shared__ float Bs[8][128];

    const int tid  = threadIdx.x;
    const int row0 = blockIdx.y * 128;
    const int col0 = blockIdx.x * 128;

    const int arow = tid >> 1;
    const int acol = (tid & 1) * 4;
    const int gr   = row0 + arow;
    const float* Arow = A + (size_t)(gr / rowsPerBatch) * batchStrideA
                          + (size_t)(gr % rowsPerBatch) * K;

    const int brow = tid >> 5;
    const int bcol = (tid & 31) * 4;

    const int tx = tid & 15;
    const int ty = tid >> 4;

    float acc[8][8];
    #pragma unroll
    for (int i = 0; i < 8; i++)
        #pragma unroll
        for (int j = 0; j < 8; j++) acc[i][j] = 0.f;

    for (int k0 = 0; k0 < K; k0 += 8) {
        float4 av = *(const float4*)(Arow + k0 + acol);
        As[acol + 0][arow] = av.x;
        As[acol + 1][arow] = av.y;
        As[acol + 2][arow] = av.z;
        As[acol + 3][arow] = av.w;
        *(float4*)&Bs[brow][bcol] =
            *(const float4*)(B + (size_t)(k0 + brow) * N + col0 + bcol);
        __syncthreads();
        #pragma unroll
        for (int kk = 0; kk < 8; kk++) {
            float4 a0 = *(const float4*)&As[kk][ty * 8];
            float4 a1 = *(const float4*)&As[kk][ty * 8 + 4];
            float4 b0 = *(const float4*)&Bs[kk][tx * 8];
            float4 b1 = *(const float4*)&Bs[kk][tx * 8 + 4];
            float ar[8] = {a0.x, a0.y, a0.z, a0.w, a1.x, a1.y, a1.z, a1.w};
            float br[8] = {b0.x, b0.y, b0.z, b0.w, b1.x, b1.y, b1.z, b1.w};
            #pragma unroll
            for (int i = 0; i < 8; i++)
                #pragma unroll
                for (int j = 0; j < 8; j++)
                    acc[i][j] = fmaf(ar[i], br[j], acc[i][j]);
        }
        __syncthreads();
    }
    #pragma unroll
    for (int i = 0; i < 8; i++) {
        float* Crow = C + (size_t)(row0 + ty * 8 + i) * N + col0 + tx * 8;
        *(float4*)(Crow)     = make_float4(acc[i][0], acc[i][1], acc[i][2], acc[i][3]);
        *(float4*)(Crow + 4) = make_float4(acc[i][4], acc[i][5], acc[i][6], acc[i][7]);
    }
}

// ----------------------------------------------------------------------------
// RMSNorm (full 1536-dim row) + 3D RoPE + scatter to [B, NH, L, HD]
// grid: (B*L, 2)  y: 0 = q, 1 = k.  block: 256
// ----------------------------------------------------------------------------
__global__ __launch_bounds__(256) void rope_norm_kernel(
    const float* __restrict__ nwqc, const float* __restrict__ nwqx,
    const float* __restrict__ nwkc, const float* __restrict__ nwkx)
{
    const int which = blockIdx.y;         // 0 = q, 1 = k
    const int rl = blockIdx.x;            // b*2048 + l
    const int b = rl >> 11;
    const int l = rl & 2047;

    const float* src;
    const float* nw;
    if (l < 1024) {
        src = g_tmp[which] + (size_t)(b * 1024 + l) * DM;          // cond stream
        nw  = which ? nwkc : nwqc;
    } else {
        src = g_tmp[3 + which] + (size_t)(b * 1024 + l - 1024) * DM;  // x stream
        nw  = which ? nwkx : nwqx;
    }

    __shared__ float srow[DM];
    __shared__ float red[256];

    float ss = 0.f;
    for (int c = threadIdx.x; c < DM; c += 256) {
        float v = src[c];
        srow[c] = v;
        ss += v * v;
    }
    red[threadIdx.x] = ss;
    __syncthreads();
    for (int s = 128; s > 0; s >>= 1) {
        if (threadIdx.x < s) red[threadIdx.x] += red[threadIdx.x + s];
        __syncthreads();
    }
    const float rms = rsqrtf(red[0] * (1.0f / DM) + EPSF);

    // position decomposition: l = t*H*W + h*W + w with T=2, H=W=32
    const float pt = (float)(l >> 10);
    const float ph = (float)((l >> 5) & 31);
    const float pw = (float)(l & 31);
    const float lnstep = 0.57564627324851148f;   // ln(10000)/16

    float* dst = which ? g_kk : g_q;
    for (int c = threadIdx.x; c < DM; c += 256) {
        int head = c / HD;
        int d = c - head * HD;
        int axis = d / 32;
        int i = d - axis * 32;
        int j = i & 15;
        float pos = (axis == 0) ? pt : (axis == 1) ? ph : pw;
        float invf = expf(-(float)j * lnstep);
        float ang = pos * invf;
        float sv, cv;
        sincosf(ang, &sv, &cv);
        float v  = srow[c] * rms * nw[c];
        int pc   = (i < 16) ? c + 16 : c - 16;
        float vp = srow[pc] * rms * nw[pc];
        float rot = (i < 16) ? -vp : vp;
        float outv = v * cv + rot * sv;
        dst[((size_t)(b * NHD + head) * LT + l) * HD + d] = outv;
    }
}

// ----------------------------------------------------------------------------
// V pack: g_tmp[2]/g_tmp[5] -> g_v [B, NH, L, HD]
// ----------------------------------------------------------------------------
__global__ __launch_bounds__(256) void vpack_kernel()
{
    int idx = blockIdx.x * 256 + threadIdx.x;      // < 2*2048*1536
    int c  = idx % DM;
    int rl = idx / DM;
    int b = rl >> 11;
    int l = rl & 2047;
    float v;
    if (l < 1024) v = g_tmp[2][(size_t)(b * 1024 + l) * DM + c];
    else          v = g_tmp[5][(size_t)(b * 1024 + l - 1024) * DM + c];
    int head = c / HD;
    int d = c - head * HD;
    g_v[((size_t)(b * NHD + head) * LT + l) * HD + d] = v;
}

// ----------------------------------------------------------------------------
// Flash attention fp32.  Br=128, Bc=64, d=96.  256 threads, dynamic smem.
// grid: (L/128, NH, B)
// smem layout (floats):
//   Qs  [96][132]  (transposed, scale folded in)      12672
//   KV  union: Kt [96][65] (6240) / Vs [64][100] (6395) -> 6400
//   Ss  [64][129]  (S^T: [col][row])                   8256
//   m/l/f rows 3*128                                    384
// total 27712 floats = 110848 B  (<= 114KB -> 2 blocks/SM)
// ----------------------------------------------------------------------------
#define ATTN_SMEM_FLOATS (96*132 + 6400 + 64*129 + 384)
#define ATTN_SMEM_BYTES  (ATTN_SMEM_FLOATS * 4)

__global__ __launch_bounds__(256, 2) void attn_kernel()
{
    extern __shared__ float smem[];
    float* Qs   = smem;                    // [96][132]
    float* KV   = Qs + 96 * 132;           // union
    float* Ss   = KV + 6400;               // [64][129]
    float* mrow = Ss + 64 * 129;           // [128]
    float* lrow = mrow + 128;
    float* frow = lrow + 128;

    const int tid = threadIdx.x;
    const int b = blockIdx.z;
    const int h = blockIdx.y;
    const int q0 = blockIdx.x * 128;

    const float* Qb = g_q  + ((size_t)(b * NHD + h) * LT + q0) * HD;
    const float* Kb = g_kk + ((size_t)(b * NHD + h) * LT) * HD;
    const float* Vb = g_v  + ((size_t)(b * NHD + h) * LT) * HD;

    // load Q tile transposed, scale folded
    for (int i = tid; i < 128 * 24; i += 256) {
        int r = i / 24;
        int c4 = (i - r * 24) * 4;
        float4 v = *(const float4*)(Qb + (size_t)r * HD + c4);
        Qs[(c4 + 0) * 132 + r] = v.x * SCALEF;
        Qs[(c4 + 1) * 132 + r] = v.y * SCALEF;
        Qs[(c4 + 2) * 132 + r] = v.z * SCALEF;
        Qs[(c4 + 3) * 132 + r] = v.w * SCALEF;
    }
    if (tid < 128) { mrow[tid] = -1e30f; lrow[tid] = 0.f; }

    const int sx = tid & 15;   // S-phase: cols sx*4..+3
    const int sy = tid >> 4;   // S-phase: rows sy*8..+7
    const int ox = tid & 15;   // O-phase: cols ox*6..+5
    const int oy = tid >> 4;   // O-phase: rows oy*8..+7

    float O[8][6];
    #pragma unroll
    for (int i = 0; i < 8; i++)
        #pragma unroll
        for (int c = 0; c < 6; c++) O[i][c] = 0.f;

    __syncthreads();

    for (int kt = 0; kt < LT; kt += 64) {
        // ---- load K tile transposed: Kt[d][j], stride 65 ----
        for (int i = tid; i < 64 * 24; i += 256) {
            int r = i / 24;
            int c4 = (i - r * 24) * 4;
            float4 v = *(const float4*)(Kb + (size_t)(kt + r) * HD + c4);
            KV[(c4 + 0) * 65 + r] = v.x;
            KV[(c4 + 1) * 65 + r] = v.y;
            KV[(c4 + 2) * 65 + r] = v.z;
            KV[(c4 + 3) * 65 + r] = v.w;
        }
        __syncthreads();

        // ---- S = Q K^T (scaled) ----
        float sacc[8][4];
        #pragma unroll
        for (int i = 0; i < 8; i++)
            #pragma unroll
            for (int j = 0; j < 4; j++) sacc[i][j] = 0.f;
        #pragma unroll 4
        for (int d = 0; d < 96; d++) {
            float4 a0 = *(const float4*)&Qs[d * 132 + sy * 8];
            float4 a1 = *(const float4*)&Qs[d * 132 + sy * 8 + 4];
            float ar[8] = {a0.x, a0.y, a0.z, a0.w, a1.x, a1.y, a1.z, a1.w};
            float br[4];
            #pragma unroll
            for (int j = 0; j < 4; j++) br[j] = KV[d * 65 + sx * 4 + j];
            #pragma unroll
            for (int i = 0; i < 8; i++)
                #pragma unroll
                for (int j = 0; j < 4; j++)
                    sacc[i][j] = fmaf(ar[i], br[j], sacc[i][j]);
        }
        #pragma unroll
        for (int j = 0; j < 4; j++)
            #pragma unroll
            for (int i = 0; i < 8; i++)
                Ss[(sx * 4 + j) * 129 + sy * 8 + i] = sacc[i][j];
        __syncthreads();

        // ---- online softmax (2 threads per row) ----
        {
            int row = tid >> 1;
            int j0 = (tid & 1) * 32;
            float mx = -1e30f;
            #pragma unroll 8
            for (int j = 0; j < 32; j++)
                mx = fmaxf(mx, Ss[(j0 + j) * 129 + row]);
            mx = fmaxf(mx, __shfl_xor_sync(0xffffffffu, mx, 1));
            float mold = mrow[row];
            float mnew = fmaxf(mold, mx);
            float f = __expf(mold - mnew);
            float ps = 0.f;
            #pragma unroll 8
            for (int j = 0; j < 32; j++) {
                float p = __expf(Ss[(j0 + j) * 129 + row] - mnew);
                Ss[(j0 + j) * 129 + row] = p;
                ps += p;
            }
            ps += __shfl_xor_sync(0xffffffffu, ps, 1);
            if ((tid & 1) == 0) {
                mrow[row] = mnew;
                lrow[row] = lrow[row] * f + ps;
                frow[row] = f;
            }
        }
        __syncthreads();

        // ---- rescale O, load V tile (row-major, stride 100) ----
        {
            float fr[8];
            #pragma unroll
            for (int i = 0; i < 8; i++) fr[i] = frow[oy * 8 + i];
            #pragma unroll
            for (int i = 0; i < 8; i++)
                #pragma unroll
                for (int c = 0; c < 6; c++) O[i][c] *= fr[i];
        }
        for (int i = tid; i < 64 * 24; i += 256) {
            int r = i / 24;
            int c4 = (i - r * 24) * 4;
            float4 v = *(const float4*)(Vb + (size_t)(kt + r) * HD + c4);
            *(float4*)&KV[r * 100 + c4] = v;
        }
        __syncthreads();

        // ---- O += P V ----
        #pragma unroll 2
        for (int j = 0; j < 64; j++) {
            float p[8];
            #pragma unroll
            for (int i = 0; i < 8; i++) p[i] = Ss[j * 129 + oy * 8 + i];
            float bv[6];
            #pragma unroll
            for (int c = 0; c < 6; c++) bv[c] = KV[j * 100 + ox * 6 + c];
            #pragma unroll
            for (int i = 0; i < 8; i++)
                #pragma unroll
                for (int c = 0; c < 6; c++)
                    O[i][c] = fmaf(p[i], bv[c], O[i][c]);
        }
        __syncthreads();
    }

    // ---- finalize: divide by l, write [B, L, NH, HD] token-major ----
    float linv[8];
    #pragma unroll
    for (int i = 0; i < 8; i++) linv[i] = 1.0f / lrow[oy * 8 + i];
    #pragma unroll
    for (int i = 0; i < 8; i++) {
        int l = q0 + oy * 8 + i;
        float* dst = g_attn + ((size_t)(b * LT + l) * NHD + h) * HD + ox * 6;
        #pragma unroll
        for (int c = 0; c < 6; c++) dst[c] = O[i][c] * linv[i];
    }
}

// ----------------------------------------------------------------------------
// Launch
// ----------------------------------------------------------------------------
extern "C" void kernel_launch(void* const* d_in, const int* in_sizes, int n_in,
                              void* d_out, int out_size)
{
    const float* cond         = (const float*)d_in[0];
    const float* x            = (const float*)d_in[1];
    const float* cond_q_w     = (const float*)d_in[2];
    const float* cond_k_w     = (const float*)d_in[3];
    const float* cond_v_w     = (const float*)d_in[4];
    const float* cond_qnorm_w = (const float*)d_in[5];
    const float* cond_knorm_w = (const float*)d_in[6];
    const float* cond_proj_w  = (const float*)d_in[7];
    const float* x_q_w        = (const float*)d_in[8];
    const float* x_k_w        = (const float*)d_in[9];
    const float* x_v_w        = (const float*)d_in[10];
    const float* x_qnorm_w    = (const float*)d_in[11];
    const float* x_knorm_w    = (const float*)d_in[12];
    const float* x_proj_w     = (const float*)d_in[13];
    float* out = (float*)d_out;

    float* tmp;  cudaGetSymbolAddress((void**)&tmp,  g_tmp);
    float* attn; cudaGetSymbolAddress((void**)&attn, g_attn);

    const size_t TS = (size_t)RT * DM;     // one tmp buffer
    dim3 gg(12, 16);                        // N/128, M/128

    // Stage A: six projections (rows contiguous: [B*N, D])
    sgemm_kernel<<<gg, 256>>>(cond, cond_q_w, tmp + 0 * TS, RT, 0);
    sgemm_kernel<<<gg, 256>>>(cond, cond_k_w, tmp + 1 * TS, RT, 0);
    sgemm_kernel<<<gg, 256>>>(cond, cond_v_w, tmp + 2 * TS, RT, 0);
    sgemm_kernel<<<gg, 256>>>(x,    x_q_w,    tmp + 3 * TS, RT, 0);
    sgemm_kernel<<<gg, 256>>>(x,    x_k_w,    tmp + 4 * TS, RT, 0);
    sgemm_kernel<<<gg, 256>>>(x,    x_v_w,    tmp + 5 * TS, RT, 0);

    // RMSNorm + RoPE for q,k ; pack v
    rope_norm_kernel<<<dim3(NB * LT, 2), 256>>>(cond_qnorm_w, x_qnorm_w,
                                                cond_knorm_w, x_knorm_w);
    vpack_kernel<<<(NB * LT * DM) / 256, 256>>>();

    // Attention
    cudaFuncSetAttribute(attn_kernel, cudaFuncAttributeMaxDynamicSharedMemorySize,
                         ATTN_SMEM_BYTES);
    attn_kernel<<<dim3(LT / 128, NHD, NB), 256, ATTN_SMEM_BYTES>>>();

    // Output projections: rows (b, n) with batch stride 2048*1536 in g_attn
    const size_t bs = (size_t)LT * DM;
    sgemm_kernel<<<gg, 256>>>(attn,                    cond_proj_w, out,                 1024, bs);
    sgemm_kernel<<<gg, 256>>>(attn + (size_t)1024*DM, x_proj_w,    out + (size_t)RT*DM, 1024, bs);
}